// round 9
// baseline (speedup 1.0000x reference)
#include <cuda_runtime.h>

#define MAXP 131072
#define MAXL 16384

typedef unsigned long long u64;

// ---------------- device scratch ----------------
__device__ float g_path_state[MAXP * 32];   // [P,32]
__device__ float g_link_state[MAXL * 32];   // [L,32]
__device__ float g_link_agg[MAXL * 32];     // [L,32] segment-sum accumulator
__device__ float g_lkf[MAXL * 96];          // per-link projected input (z|r|A), biases folded
__device__ int   g_off[MAXP + 1];
__device__ int   g_order[MAXP];

// ---------------- math helpers ----------------
__device__ __forceinline__ float tanhapx_(float x) {
    float y;
    asm("tanh.approx.f32 %0, %1;" : "=f"(y) : "f"(x));
    return y;
}
__device__ __forceinline__ float sigm_(float x) {
    return fmaf(0.5f, tanhapx_(0.5f * x), 0.5f);
}
__device__ __forceinline__ float selu_(float x) {
    const float sc = 1.0507009873554805f, al = 1.6732632423543772f;
    return x > 0.f ? sc * x : sc * al * (__expf(x) - 1.f);
}
__device__ __forceinline__ void redv4(float* gp, float a, float b, float c, float d) {
    asm volatile("red.global.add.v4.f32 [%0], {%1, %2, %3, %4};"
                 :: "l"(gp), "f"(a), "f"(b), "f"(c), "f"(d) : "memory");
}
// ---- packed f32x2 ----
__device__ __forceinline__ u64 pkdup_(float v) {
    u64 r; asm("mov.b64 %0, {%1, %1};" : "=l"(r) : "f"(v)); return r;
}
__device__ __forceinline__ void upk_(u64 v, float& lo, float& hi) {
    asm("mov.b64 {%0, %1}, %2;" : "=f"(lo), "=f"(hi) : "l"(v));
}
__device__ __forceinline__ u64 ffma2_(u64 a, u64 b, u64 c) {
    u64 d; asm("fma.rn.f32x2 %0, %1, %2, %3;" : "=l"(d) : "l"(a), "l"(b), "l"(c)); return d;
}

// ---------------- launch 0: fused init ----------------
__global__ void k_init_all(const float* __restrict__ cap, const float* __restrict__ traffic,
                           const float* __restrict__ K_path, const float* __restrict__ b_path,
                           int nP, int nL)
{
    int i = blockIdx.x * blockDim.x + threadIdx.x;
    if (i < nP * 32) g_path_state[i] = ((i & 31) == 0) ? traffic[i >> 5] : 0.f;
    if (i < nL * 32) { g_link_state[i] = ((i & 31) == 0) ? cap[i >> 5] : 0.f; g_link_agg[i] = 0.f; }
    if (i < nL * 96) {
        int l = i / 96, j = i - l * 96;
        float fold = (j < 64) ? (b_path[j] + b_path[96 + j]) : b_path[j];
        g_lkf[i] = cap[l] * K_path[j] + fold;
    }
}

// ---------------- launch 1: CSR offsets ----------------
__global__ void k_offsets(const int* __restrict__ paths, int E, int nP) {
    int e = blockIdx.x * blockDim.x + threadIdx.x;
    if (e >= E) return;
    int pe = paths[e];
    if (pe < 0 || pe >= nP) return;
    if (e == 0) { g_off[nP] = E; g_off[pe] = 0; }
    else if (paths[e - 1] != pe) g_off[pe] = e;
}

// ---------------- launch 2: ordering, LONGEST length first (1 block) ----------------
__global__ void __launch_bounds__(1024) k_order_build(int nP) {
    __shared__ int scnt[256];
    int tid = threadIdx.x;
    for (int i = tid; i < 256; i += 1024) scnt[i] = 0;
    __syncthreads();
    for (int p = tid; p < nP; p += 1024) {
        int len = g_off[p + 1] - g_off[p];
        len = min(max(len, 0), 255);
        atomicAdd(&scnt[len], 1);
    }
    __syncthreads();
    if (tid == 0) {
        int b = 0;
        for (int i = 255; i >= 0; i--) { int c = scnt[i]; scnt[i] = b; b += c; }
    }
    __syncthreads();
    for (int p = tid; p < nP; p += 1024) {
        int len = g_off[p + 1] - g_off[p];
        len = min(max(len, 0), 255);
        int pos = atomicAdd(&scnt[len], 1);
        if (pos < nP) g_order[pos] = p;
    }
}

// ---------------- launch 3,5,7,9: path scan — TWO paths per thread ----------------
// Each weight LDS.128 feeds both paths (halves smem crossbar bytes per path-step).
// Sorted-descending order guarantees len(idx0) >= len(idx0+128).
// hn staged via per-thread smem scratch (no cross-thread access -> no syncs).
__global__ void __launch_bounds__(128, 3) k_path(
    const int* __restrict__ links,
    const float* __restrict__ R, const float* __restrict__ b, int nP)
{
    __shared__ __align__(16) float wR[3072];
    __shared__ __align__(16) float sb1h[32];
    __shared__ __align__(16) float scr[32 * 2 * 128];   // [j][pp][tid]
    int tid = threadIdx.x;
    for (int i = tid; i < 3072; i += 128) wR[i] = R[i];
    if (tid < 32) sb1h[tid] = b[96 + 64 + tid];

    int idx0 = blockIdx.x * 256 + tid;
    int idx1 = idx0 + 128;
    int p0 = 0, off0 = 0, len0 = 0, p1 = 0, off1 = 0, len1 = 0;
    if (idx0 < nP) { p0 = g_order[idx0]; off0 = g_off[p0]; len0 = g_off[p0 + 1] - off0; if (len0 < 0) len0 = 0; }
    if (idx1 < nP) { p1 = g_order[idx1]; off1 = g_off[p1]; len1 = g_off[p1 + 1] - off1; if (len1 < 0) len1 = 0; }
    else p1 = p0;   // safe address for speculative loads; never stored
    __syncthreads();
    if (idx0 >= nP) return;

    float h0[32], h1[32];
    {
        const float4* hp0 = (const float4*)(g_path_state + p0 * 32);
        const float4* hp1 = (const float4*)(g_path_state + p1 * 32);
#pragma unroll
        for (int q = 0; q < 8; q++) {
            float4 v = hp0[q];
            h0[4 * q] = v.x; h0[4 * q + 1] = v.y; h0[4 * q + 2] = v.z; h0[4 * q + 3] = v.w;
            float4 u = hp1[q];
            h1[4 * q] = u.x; h1[4 * q + 1] = u.y; h1[4 * q + 2] = u.z; h1[4 * q + 3] = u.w;
        }
    }

    int lk0 = (len0 > 0) ? __ldg(links + off0) : 0;
    int lk1 = (len1 > 0) ? __ldg(links + off1) : 0;
    {
        const float* Ln = g_lkf + lk0 * 96;
        asm volatile("prefetch.global.L1 [%0];" :: "l"(Ln));
        asm volatile("prefetch.global.L1 [%0];" :: "l"(Ln + 32));
        asm volatile("prefetch.global.L1 [%0];" :: "l"(Ln + 64));
        const float* Lm = g_lkf + lk1 * 96;
        asm volatile("prefetch.global.L1 [%0];" :: "l"(Lm));
        asm volatile("prefetch.global.L1 [%0];" :: "l"(Lm + 32));
        asm volatile("prefetch.global.L1 [%0];" :: "l"(Lm + 64));
    }

    for (int s = 0; s < len0; s++) {
        bool a1 = (s < len1);
        int lk0n = (s + 1 < len0) ? __ldg(links + off0 + s + 1) : 0;
        int lk1n = (s + 1 < len1) ? __ldg(links + off1 + s + 1) : 0;
        {
            const float* Ln = g_lkf + lk0n * 96;
            asm volatile("prefetch.global.L1 [%0];" :: "l"(Ln));
            asm volatile("prefetch.global.L1 [%0];" :: "l"(Ln + 32));
            asm volatile("prefetch.global.L1 [%0];" :: "l"(Ln + 64));
            const float* Lm = g_lkf + lk1n * 96;
            asm volatile("prefetch.global.L1 [%0];" :: "l"(Lm));
            asm volatile("prefetch.global.L1 [%0];" :: "l"(Lm + 32));
            asm volatile("prefetch.global.L1 [%0];" :: "l"(Lm + 64));
        }
        const float* L0 = g_lkf + lk0 * 96;
        const float* L1 = g_lkf + lk1 * 96;
        float* agg0 = g_link_agg + lk0 * 32;
        float* agg1 = g_link_agg + lk1 * 32;

        for (int e = 0; e < 8; e++) {
            const int j0 = e * 4;
            u64 az0[2], ar0[2], bb0[2], az1[2], ar1[2], bb1[2];
            float A0[4], A1[4];
            {
                ulonglong2 vz0 = *(const ulonglong2*)(L0 + j0);
                az0[0] = vz0.x; az0[1] = vz0.y;
                ulonglong2 vr0 = *(const ulonglong2*)(L0 + 32 + j0);
                ar0[0] = vr0.x; ar0[1] = vr0.y;
                float4 va0 = *(const float4*)(L0 + 64 + j0);
                A0[0] = va0.x; A0[1] = va0.y; A0[2] = va0.z; A0[3] = va0.w;
                ulonglong2 vz1 = *(const ulonglong2*)(L1 + j0);
                az1[0] = vz1.x; az1[1] = vz1.y;
                ulonglong2 vr1 = *(const ulonglong2*)(L1 + 32 + j0);
                ar1[0] = vr1.x; ar1[1] = vr1.y;
                float4 va1 = *(const float4*)(L1 + 64 + j0);
                A1[0] = va1.x; A1[1] = va1.y; A1[2] = va1.z; A1[3] = va1.w;
                ulonglong2 bi = *(const ulonglong2*)(sb1h + j0);
                bb0[0] = bi.x; bb0[1] = bi.y;
                bb1[0] = bi.x; bb1[1] = bi.y;
            }
#pragma unroll 8
            for (int i = 0; i < 32; i++) {
                ulonglong2 wz = *(const ulonglong2*)(wR + i * 96 + j0);
                ulonglong2 wr = *(const ulonglong2*)(wR + i * 96 + 32 + j0);
                ulonglong2 wh = *(const ulonglong2*)(wR + i * 96 + 64 + j0);
                u64 h20 = pkdup_(h0[i]);
                u64 h21 = pkdup_(h1[i]);
                az0[0] = ffma2_(h20, wz.x, az0[0]); az0[1] = ffma2_(h20, wz.y, az0[1]);
                ar0[0] = ffma2_(h20, wr.x, ar0[0]); ar0[1] = ffma2_(h20, wr.y, ar0[1]);
                bb0[0] = ffma2_(h20, wh.x, bb0[0]); bb0[1] = ffma2_(h20, wh.y, bb0[1]);
                az1[0] = ffma2_(h21, wz.x, az1[0]); az1[1] = ffma2_(h21, wz.y, az1[1]);
                ar1[0] = ffma2_(h21, wr.x, ar1[0]); ar1[1] = ffma2_(h21, wr.y, ar1[1]);
                bb1[0] = ffma2_(h21, wh.x, bb1[0]); bb1[1] = ffma2_(h21, wh.y, bb1[1]);
            }
            // epilogue: gates + hn -> scratch, REDG directly from regs
            float hn0[4], hn1[4];
#pragma unroll
            for (int q = 0; q < 2; q++) {
                float zl, zh, rl, rh, bl, bh;
                upk_(az0[q], zl, zh); upk_(ar0[q], rl, rh); upk_(bb0[q], bl, bh);
                float za = sigm_(zl), zb = sigm_(zh);
                float ra = sigm_(rl), rb = sigm_(rh);
                float ha = tanhapx_(A0[2 * q] + ra * bl);
                float hb = tanhapx_(A0[2 * q + 1] + rb * bh);
                hn0[2 * q]     = za * h0[j0 + 2 * q]     + (1.f - za) * ha;
                hn0[2 * q + 1] = zb * h0[j0 + 2 * q + 1] + (1.f - zb) * hb;
                upk_(az1[q], zl, zh); upk_(ar1[q], rl, rh); upk_(bb1[q], bl, bh);
                za = sigm_(zl); zb = sigm_(zh);
                ra = sigm_(rl); rb = sigm_(rh);
                ha = tanhapx_(A1[2 * q] + ra * bl);
                hb = tanhapx_(A1[2 * q + 1] + rb * bh);
                hn1[2 * q]     = za * h1[j0 + 2 * q]     + (1.f - za) * ha;
                hn1[2 * q + 1] = zb * h1[j0 + 2 * q + 1] + (1.f - zb) * hb;
            }
#pragma unroll
            for (int u = 0; u < 4; u++) {
                scr[((j0 + u) * 2 + 0) * 128 + tid] = hn0[u];
                scr[((j0 + u) * 2 + 1) * 128 + tid] = hn1[u];
            }
            redv4(agg0 + j0, hn0[0], hn0[1], hn0[2], hn0[3]);
            if (a1) redv4(agg1 + j0, hn1[0], hn1[1], hn1[2], hn1[3]);
        }
        // commit new states from scratch
#pragma unroll
        for (int j = 0; j < 32; j++) h0[j] = scr[(j * 2) * 128 + tid];
        if (a1) {
#pragma unroll
            for (int j = 0; j < 32; j++) h1[j] = scr[(j * 2 + 1) * 128 + tid];
        }
        lk0 = lk0n; lk1 = lk1n;
    }

    {
        float4* ho = (float4*)(g_path_state + p0 * 32);
#pragma unroll
        for (int q = 0; q < 8; q++)
            ho[q] = make_float4(h0[4 * q], h0[4 * q + 1], h0[4 * q + 2], h0[4 * q + 3]);
    }
    if (idx1 < nP) {
        float4* ho = (float4*)(g_path_state + p1 * 32);
#pragma unroll
        for (int q = 0; q < 8; q++)
            ho[q] = make_float4(h1[4 * q], h1[4 * q + 1], h1[4 * q + 2], h1[4 * q + 3]);
    }
}

// ---------------- launch 4,6,8,10: link GRU — 2 threads per link (j-halves) ----------------
__global__ void __launch_bounds__(128) k_link(
    const float* __restrict__ K, const float* __restrict__ R, const float* __restrict__ b,
    const float* __restrict__ K_path, const float* __restrict__ b_path, int nL)
{
    __shared__ __align__(16) float wK[3072], wRR[3072], wKp[3072];
    __shared__ __align__(16) float sb0[96], sb1[96], sfold[96];
    __shared__ __align__(16) float shn[32 * 64];   // [j][link-in-block]
    int t = threadIdx.x;
    int li = t & 63, half = t >> 6;
    int l = blockIdx.x * 64 + li;
    for (int i = t; i < 3072; i += 128) { wK[i] = K[i]; wRR[i] = R[i]; wKp[i] = K_path[i]; }
    if (t < 96) {
        sb0[t] = b[t]; sb1[t] = b[96 + t];
        sfold[t] = (t < 64) ? (b_path[t] + b_path[96 + t]) : b_path[t];
    }
    __syncthreads();
    bool ok = (l < nL);

    float x[32], h[32];
    if (ok) {
        const float4* xp = (const float4*)(g_link_agg + l * 32);
        const float4* hp = (const float4*)(g_link_state + l * 32);
#pragma unroll
        for (int q = 0; q < 8; q++) {
            float4 v = xp[q];
            x[4 * q] = v.x; x[4 * q + 1] = v.y; x[4 * q + 2] = v.z; x[4 * q + 3] = v.w;
            float4 u = hp[q];
            h[4 * q] = u.x; h[4 * q + 1] = u.y; h[4 * q + 2] = u.z; h[4 * q + 3] = u.w;
        }
    } else {
#pragma unroll
        for (int j = 0; j < 32; j++) { x[j] = 0.f; h[j] = 0.f; }
    }

    // this thread computes gate outputs for j in [half*16, half*16+16)
    const int j0 = half * 16;
    float hn[16];
    {
        float az[16], ar[16], A[16], B[16];
#pragma unroll
        for (int j = 0; j < 16; j++) {
            az[j] = sb0[j0 + j] + sb1[j0 + j];
            ar[j] = sb0[32 + j0 + j] + sb1[32 + j0 + j];
            A[j]  = sb0[64 + j0 + j];
            B[j]  = sb1[64 + j0 + j];
        }
#pragma unroll 4
        for (int i = 0; i < 32; i++) {
            float xi = x[i], hi = h[i];
            const float4* kz = (const float4*)(wK + i * 96 + j0);
            const float4* kr = (const float4*)(wK + i * 96 + 32 + j0);
            const float4* kh = (const float4*)(wK + i * 96 + 64 + j0);
            const float4* rz = (const float4*)(wRR + i * 96 + j0);
            const float4* rr = (const float4*)(wRR + i * 96 + 32 + j0);
            const float4* rh = (const float4*)(wRR + i * 96 + 64 + j0);
#pragma unroll
            for (int q = 0; q < 4; q++) {
                float4 a = kz[q], c = rz[q];
                az[4 * q + 0] = fmaf(xi, a.x, fmaf(hi, c.x, az[4 * q + 0]));
                az[4 * q + 1] = fmaf(xi, a.y, fmaf(hi, c.y, az[4 * q + 1]));
                az[4 * q + 2] = fmaf(xi, a.z, fmaf(hi, c.z, az[4 * q + 2]));
                az[4 * q + 3] = fmaf(xi, a.w, fmaf(hi, c.w, az[4 * q + 3]));
                float4 d = kr[q], e = rr[q];
                ar[4 * q + 0] = fmaf(xi, d.x, fmaf(hi, e.x, ar[4 * q + 0]));
                ar[4 * q + 1] = fmaf(xi, d.y, fmaf(hi, e.y, ar[4 * q + 1]));
                ar[4 * q + 2] = fmaf(xi, d.z, fmaf(hi, e.z, ar[4 * q + 2]));
                ar[4 * q + 3] = fmaf(xi, d.w, fmaf(hi, e.w, ar[4 * q + 3]));
                float4 f = kh[q], g = rh[q];
                A[4 * q + 0] = fmaf(xi, f.x, A[4 * q + 0]);
                A[4 * q + 1] = fmaf(xi, f.y, A[4 * q + 1]);
                A[4 * q + 2] = fmaf(xi, f.z, A[4 * q + 2]);
                A[4 * q + 3] = fmaf(xi, f.w, A[4 * q + 3]);
                B[4 * q + 0] = fmaf(hi, g.x, B[4 * q + 0]);
                B[4 * q + 1] = fmaf(hi, g.y, B[4 * q + 1]);
                B[4 * q + 2] = fmaf(hi, g.z, B[4 * q + 2]);
                B[4 * q + 3] = fmaf(hi, g.w, B[4 * q + 3]);
            }
        }
#pragma unroll
        for (int j = 0; j < 16; j++) {
            float z = sigm_(az[j]);
            float r = sigm_(ar[j]);
            float hh = tanhapx_(A[j] + r * B[j]);
            hn[j] = z * h[j0 + j] + (1.f - z) * hh;
        }
    }

    // publish hn half; write state half; rezero agg half
#pragma unroll
    for (int j = 0; j < 16; j++) shn[(j0 + j) * 64 + li] = hn[j];
    if (ok) {
        float4* ho = (float4*)(g_link_state + l * 32 + j0);
        float4* ao = (float4*)(g_link_agg + l * 32 + j0);
#pragma unroll
        for (int q = 0; q < 4; q++) {
            ho[q] = make_float4(hn[4 * q], hn[4 * q + 1], hn[4 * q + 2], hn[4 * q + 3]);
            ao[q] = make_float4(0.f, 0.f, 0.f, 0.f);
        }
    }
    __syncthreads();

    // LKf half: cols [half*48, half*48+48) of hn_full @ K_path + fold
    if (ok) {
        float hf[32];
#pragma unroll
        for (int j = 0; j < 32; j++) hf[j] = shn[j * 64 + li];
        float* Lout = g_lkf + l * 96;
#pragma unroll
        for (int c = 0; c < 3; c++) {
            int cc = half * 48 + c * 16;
            float acc[16];
#pragma unroll
            for (int j = 0; j < 16; j++) acc[j] = sfold[cc + j];
#pragma unroll 4
            for (int i = 0; i < 32; i++) {
                float hi = hf[i];
                const float4* w = (const float4*)(wKp + i * 96 + cc);
#pragma unroll
                for (int q = 0; q < 4; q++) {
                    float4 a = w[q];
                    acc[4 * q + 0] = fmaf(hi, a.x, acc[4 * q + 0]);
                    acc[4 * q + 1] = fmaf(hi, a.y, acc[4 * q + 1]);
                    acc[4 * q + 2] = fmaf(hi, a.z, acc[4 * q + 2]);
                    acc[4 * q + 3] = fmaf(hi, a.w, acc[4 * q + 3]);
                }
            }
#pragma unroll
            for (int q = 0; q < 4; q++)
                *(float4*)(Lout + cc + 4 * q) =
                    make_float4(acc[4 * q], acc[4 * q + 1], acc[4 * q + 2], acc[4 * q + 3]);
        }
    }
}

// ---------------- readout (last launch, FFMA2 column-pair scheme) ----------------
#define RO_SPS   (32 * 68)
#define RO_SW    (32 * 256)
#define RO_SH    (256 * 68)
#define RO_SMEM_BYTES ((RO_SPS + RO_SW + RO_SH) * 4)

__global__ void __launch_bounds__(256) k_readout(
    const float* __restrict__ W1, const float* __restrict__ b1v,
    const float* __restrict__ W2, const float* __restrict__ b2v,
    const float* __restrict__ Wf, const float* __restrict__ bfv,
    float* __restrict__ out, int nP)
{
    extern __shared__ float sm[];
    float* s_ps = sm;                  // [32][68]
    float* s_w  = sm + RO_SPS;         // [32][256]
    float* s_h  = sm + RO_SPS + RO_SW; // [256][68]

    int tx = threadIdx.x;
    int rg = tx >> 4, cg = tx & 15;
    int r0 = rg * 4;
    int c0 = 2 * cg;
    int p0 = blockIdx.x * 64;
    int nrows = nP - p0; if (nrows > 64) nrows = 64;

    for (int idx = tx; idx < 64 * 32; idx += 256) {
        int r = idx >> 5, k = idx & 31;
        float v = (r < nrows) ? g_path_state[(p0 + r) * 32 + k] : 0.f;
        s_ps[k * 68 + r] = v;
    }
    for (int idx = tx; idx < 32 * 256 / 4; idx += 256)
        ((float4*)s_w)[idx] = ((const float4*)W1)[idx];
    __syncthreads();

    u64 acc[8][4];
#pragma unroll
    for (int v = 0; v < 8; v++)
#pragma unroll
        for (int u = 0; u < 4; u++) acc[v][u] = 0ull;
    for (int k = 0; k < 32; k++) {
        float4 a = *(const float4*)(s_ps + k * 68 + r0);
        u64 ax = pkdup_(a.x), ay = pkdup_(a.y), az = pkdup_(a.z), aw = pkdup_(a.w);
        const float* wrow = s_w + k * 256 + c0;
#pragma unroll
        for (int v = 0; v < 8; v++) {
            u64 w2 = *(const u64*)(wrow + 32 * v);
            acc[v][0] = ffma2_(ax, w2, acc[v][0]);
            acc[v][1] = ffma2_(ay, w2, acc[v][1]);
            acc[v][2] = ffma2_(az, w2, acc[v][2]);
            acc[v][3] = ffma2_(aw, w2, acc[v][3]);
        }
    }
#pragma unroll
    for (int v = 0; v < 8; v++) {
        float2 bb = *(const float2*)(b1v + c0 + 32 * v);
        float lo[4], hi[4];
#pragma unroll
        for (int u = 0; u < 4; u++) {
            float l_, h_;
            upk_(acc[v][u], l_, h_);
            lo[u] = selu_(l_ + bb.x);
            hi[u] = selu_(h_ + bb.y);
        }
        *(float4*)(s_h + (c0 + 32 * v) * 68 + r0)     = make_float4(lo[0], lo[1], lo[2], lo[3]);
        *(float4*)(s_h + (c0 + 32 * v + 1) * 68 + r0) = make_float4(hi[0], hi[1], hi[2], hi[3]);
    }
    __syncthreads();

    u64 acc2[8][4];
#pragma unroll
    for (int v = 0; v < 8; v++)
#pragma unroll
        for (int u = 0; u < 4; u++) acc2[v][u] = 0ull;
    for (int kt = 0; kt < 8; kt++) {
        for (int idx = tx; idx < 32 * 256 / 4; idx += 256)
            ((float4*)s_w)[idx] = ((const float4*)(W2 + kt * 32 * 256))[idx];
        __syncthreads();
        for (int kk = 0; kk < 32; kk++) {
            int k = kt * 32 + kk;
            float4 a = *(const float4*)(s_h + k * 68 + r0);
            u64 ax = pkdup_(a.x), ay = pkdup_(a.y), az = pkdup_(a.z), aw = pkdup_(a.w);
            const float* wrow = s_w + kk * 256 + c0;
#pragma unroll
            for (int v = 0; v < 8; v++) {
                u64 w2 = *(const u64*)(wrow + 32 * v);
                acc2[v][0] = ffma2_(ax, w2, acc2[v][0]);
                acc2[v][1] = ffma2_(ay, w2, acc2[v][1]);
                acc2[v][2] = ffma2_(az, w2, acc2[v][2]);
                acc2[v][3] = ffma2_(aw, w2, acc2[v][3]);
            }
        }
        __syncthreads();
    }
#pragma unroll
    for (int v = 0; v < 8; v++) {
        float2 bb = *(const float2*)(b2v + c0 + 32 * v);
        float lo[4], hi[4];
#pragma unroll
        for (int u = 0; u < 4; u++) {
            float l_, h_;
            upk_(acc2[v][u], l_, h_);
            lo[u] = selu_(l_ + bb.x);
            hi[u] = selu_(h_ + bb.y);
        }
        *(float4*)(s_h + (c0 + 32 * v) * 68 + r0)     = make_float4(lo[0], lo[1], lo[2], lo[3]);
        *(float4*)(s_h + (c0 + 32 * v + 1) * 68 + r0) = make_float4(hi[0], hi[1], hi[2], hi[3]);
    }
    __syncthreads();

    if (tx < 128) {
        int p = tx >> 1, o = tx & 1;
        if (p < nrows) {
            float s = bfv[o];
            for (int i = 0; i < 256; i++) s = fmaf(s_h[i * 68 + p], Wf[i * 2 + o], s);
            for (int j = 0; j < 32; j++)  s = fmaf(s_ps[j * 68 + p], Wf[(256 + j) * 2 + o], s);
            out[(p0 + p) * 2 + o] = s;
        }
    }
}

// ---------------- host ----------------
extern "C" void kernel_launch(void* const* d_in, const int* in_sizes, int n_in,
                              void* d_out, int out_size)
{
    const float* cap     = (const float*)d_in[0];
    const float* traffic = (const float*)d_in[1];
    const int*   links   = (const int*)d_in[2];
    const int*   paths   = (const int*)d_in[3];

    int nL = in_sizes[0];
    int nP = in_sizes[1];
    int E  = in_sizes[2];
    if (nP > MAXP) nP = MAXP;
    if (nL > MAXL) nL = MAXL;

    int wi = 5;
    for (int i = 3; i < n_in; i++) {
        if (in_sizes[i] == 3072) { wi = i; break; }
    }
    const float* K_link = (const float*)d_in[wi + 0];
    const float* R_link = (const float*)d_in[wi + 1];
    const float* b_link = (const float*)d_in[wi + 2];
    const float* K_path = (const float*)d_in[wi + 3];
    const float* R_path = (const float*)d_in[wi + 4];
    const float* b_path = (const float*)d_in[wi + 5];
    const float* W1     = (const float*)d_in[wi + 6];
    const float* b1v    = (const float*)d_in[wi + 7];
    const float* W2     = (const float*)d_in[wi + 8];
    const float* b2v    = (const float*)d_in[wi + 9];
    const float* Wf     = (const float*)d_in[wi + 10];
    const float* bfv    = (const float*)d_in[wi + 11];
    float* out = (float*)d_out;

    cudaFuncSetAttribute(k_readout, cudaFuncAttributeMaxDynamicSharedMemorySize, RO_SMEM_BYTES);

    // launches 0-2: init + ordering  (launch index 3 = first k_path -> ncu target)
    k_init_all<<<(nP * 32 + 255) / 256, 256>>>(cap, traffic, K_path, b_path, nP, nL);
    k_offsets<<<(E + 255) / 256, 256>>>(paths, E, nP);
    k_order_build<<<1, 1024>>>(nP);

    // launches 3-10: T=4 message-passing iterations
    for (int it = 0; it < 4; it++) {
        k_path<<<(nP + 255) / 256, 128>>>(links, R_path, b_path, nP);
        k_link<<<(nL + 63) / 64, 128>>>(K_link, R_link, b_link, K_path, b_path, nL);
    }

    // launch 11: readout
    k_readout<<<(nP + 63) / 64, 256, RO_SMEM_BYTES>>>(W1, b1v, W2, b2v, Wf, bfv, out, nP);
}